// round 4
// baseline (speedup 1.0000x reference)
#include <cuda_runtime.h>

#define NN 2048
#define CC 128
#define NSPEC 10
#define DD 9
#define NM_TOT 219          // 9 (deg1) + 45 (deg2) + 165 (deg3)
#define P2STRIDE 20         // floats per monomial: 9 duplicated f32 pairs + 2 pad
#define PROW2 (NM_TOT * P2STRIDE)   // 4380 floats per (species, channel)
#define MAXG64 42           // max 64-node groups: 2048/64 + 10

// Scratch (no cudaMalloc allowed)
__device__ float g_P2[(size_t)NSPEC * CC * PROW2];  // ~22.4 MB, (p,p)-duplicated
__device__ int   g_list[MAXG64 * 64];
__device__ int   g_gspec[MAXG64];

// ---------------------------------------------------------------------------
// Monomial ordering: m 0..8 = deg1(a); then for a<=b: deg2(a,b), then for
// j>=b: deg3(a,b,j). Must match the main kernel's unrolled loop.
// ---------------------------------------------------------------------------
__device__ __forceinline__ void decode_m(int m, int& deg, int& A, int& B, int& J, int& sidx)
{
    if (m < 9) { deg = 1; A = m; B = 0; J = 0; sidx = m; return; }
    int mm = 9, s2 = 0, s3 = 0;
    for (int a = 0; a < 9; a++) {
        for (int b = a; b < 9; b++) {
            if (mm == m) { deg = 2; A = a; B = b; J = 0; sidx = s2; return; }
            mm++; s2++;
            for (int j = b; j < 9; j++) {
                if (mm == m) { deg = 3; A = a; B = b; J = j; sidx = s3; return; }
                mm++; s3++;
            }
        }
    }
    deg = 0; A = B = J = sidx = 0;
}

// ---------------------------------------------------------------------------
// Kernel A: bucket nodes by species into 64-aligned groups (padded with -1)
// ---------------------------------------------------------------------------
__global__ void bucket_kernel(const int* __restrict__ index)
{
    __shared__ int cnt[NSPEC];
    __shared__ int cur[NSPEC];
    int t = threadIdx.x;
    if (t < NSPEC) cnt[t] = 0;
    __syncthreads();
    for (int n = t; n < NN; n += blockDim.x) atomicAdd(&cnt[index[n]], 1);
    __syncthreads();
    if (t == 0) {
        int off = 0, g = 0;
        for (int s = 0; s < NSPEC; s++) {
            cur[s] = off;
            int grp = (cnt[s] + 63) >> 6;
            for (int k = 0; k < grp; k++) g_gspec[g++] = s;
            off += grp * 64;
        }
        for (; g < MAXG64; g++) g_gspec[g] = -1;
    }
    __syncthreads();
    for (int i = t; i < MAXG64 * 64; i += blockDim.x) g_list[i] = -1;
    __syncthreads();
    for (int n = t; n < NN; n += blockDim.x) {
        int s = index[n];
        int p = atomicAdd(&cur[s], 1);
        g_list[p] = n;
    }
}

// ---------------------------------------------------------------------------
// Kernel B: fused U-symmetrize + weight contraction -> duplicated P table
//   g_P2[s][c][m][2i],[2i+1] = P(s,c,m,i)   (pairs for fma.rn.f32x2)
// grid = (219, 10), block = 128 (c)
// ---------------------------------------------------------------------------
__global__ void pbuild_kernel(const float* __restrict__ U3_0e, const float* __restrict__ U3_1o,
                              const float* __restrict__ U3_2e,
                              const float* __restrict__ U2_0e, const float* __restrict__ U2_1o,
                              const float* __restrict__ U2_2e,
                              const float* __restrict__ U1_0e, const float* __restrict__ U1_1o,
                              const float* __restrict__ U1_2e,
                              const float* __restrict__ W3_0e, const float* __restrict__ W3_1o,
                              const float* __restrict__ W3_2e,
                              const float* __restrict__ W2_0e, const float* __restrict__ W2_1o,
                              const float* __restrict__ W2_2e,
                              const float* __restrict__ W1_0e, const float* __restrict__ W1_1o,
                              const float* __restrict__ W1_2e)
{
    int m = blockIdx.x;
    int s = blockIdx.y;
    int t = threadIdx.x;
    int deg, A, B, J, sidx;
    decode_m(m, deg, A, B, J, sidx);

    __shared__ float su[108];   // symmetrized U row for this monomial

    // --- symmetrize U over permutations of contracted D-indices ---
    if (deg == 1) {
        if (t < 9) {
            float v;
            if (t == 0)      v = U1_0e[A];
            else if (t < 4)  v = U1_1o[A * 3 + (t - 1)];
            else             v = U1_2e[A * 5 + (t - 4)];
            su[t] = v;
        }
    } else if (deg == 2) {
        if (t < 24) {
            int e = t;
            float acc = 0.f;
            int np = (A == B) ? 1 : 2;
            for (int p = 0; p < np; p++) {
                int pa = p ? B : A;
                int pb = p ? A : B;
                int base2 = pa * 9 + pb;
                float v;
                if (e < 3) {
                    v = U2_0e[base2 * 3 + e];
                } else if (e < 9) {
                    int k = (e - 3) / 3, i = (e - 3) % 3;
                    v = U2_1o[(base2 * 2 + k) * 3 + i];
                } else {
                    int k = (e - 9) / 5, i = (e - 9) % 5;
                    v = U2_2e[(base2 * 3 + k) * 5 + i];
                }
                acc += v;
            }
            su[e] = acc;
        }
    } else { // deg 3
        if (t < 108) {
            int e = t;
            int perm[6][3];
            int np;
            if (A == B && B == J) {
                np = 1;
                perm[0][0] = A; perm[0][1] = A; perm[0][2] = A;
            } else if (A == B) {
                np = 3;
                int P[3][3] = {{A, A, J}, {A, J, A}, {J, A, A}};
                for (int p = 0; p < 3; p++) for (int q = 0; q < 3; q++) perm[p][q] = P[p][q];
            } else if (B == J) {
                np = 3;
                int P[3][3] = {{A, B, B}, {B, A, B}, {B, B, A}};
                for (int p = 0; p < 3; p++) for (int q = 0; q < 3; q++) perm[p][q] = P[p][q];
            } else {
                np = 6;
                int P[6][3] = {{A, B, J}, {A, J, B}, {B, A, J}, {B, J, A}, {J, A, B}, {J, B, A}};
                for (int p = 0; p < 6; p++) for (int q = 0; q < 3; q++) perm[p][q] = P[p][q];
            }
            float acc = 0.f;
            for (int p = 0; p < np; p++) {
                int base3 = (perm[p][0] * 9 + perm[p][1]) * 9 + perm[p][2];
                float v;
                if (e < 10) {
                    v = U3_0e[base3 * 10 + e];
                } else if (e < 43) {
                    int k = (e - 10) / 3, i = (e - 10) % 3;
                    v = U3_1o[(base3 * 11 + k) * 3 + i];
                } else {
                    int k = (e - 43) / 5, i = (e - 43) % 5;
                    v = U3_2e[(base3 * 13 + k) * 5 + i];
                }
                acc += v;
            }
            su[e] = acc;
        }
    }
    __syncthreads();

    // --- contract with per-species weights for channel c = t ---
    int c = t;
    float acc[9];
#pragma unroll
    for (int i = 0; i < 9; i++) acc[i] = 0.f;

    if (deg == 1) {
        float w0 = W1_0e[s * CC + c];
        float w1 = W1_1o[s * CC + c];
        float w2 = W1_2e[s * CC + c];
        acc[0] = su[0] * w0;
#pragma unroll
        for (int i = 0; i < 3; i++) acc[1 + i] = su[1 + i] * w1;
#pragma unroll
        for (int i = 0; i < 5; i++) acc[4 + i] = su[4 + i] * w2;
    } else if (deg == 2) {
#pragma unroll
        for (int k = 0; k < 3; k++) {
            float w = W2_0e[(s * 3 + k) * CC + c];
            acc[0] += su[k] * w;
        }
#pragma unroll
        for (int k = 0; k < 2; k++) {
            float w = W2_1o[(s * 2 + k) * CC + c];
#pragma unroll
            for (int i = 0; i < 3; i++) acc[1 + i] += su[3 + k * 3 + i] * w;
        }
#pragma unroll
        for (int k = 0; k < 3; k++) {
            float w = W2_2e[(s * 3 + k) * CC + c];
#pragma unroll
            for (int i = 0; i < 5; i++) acc[4 + i] += su[9 + k * 5 + i] * w;
        }
    } else {
#pragma unroll
        for (int k = 0; k < 10; k++) {
            float w = W3_0e[(s * 10 + k) * CC + c];
            acc[0] += su[k] * w;
        }
#pragma unroll
        for (int k = 0; k < 11; k++) {
            float w = W3_1o[(s * 11 + k) * CC + c];
#pragma unroll
            for (int i = 0; i < 3; i++) acc[1 + i] += su[10 + k * 3 + i] * w;
        }
#pragma unroll
        for (int k = 0; k < 13; k++) {
            float w = W3_2e[(s * 13 + k) * CC + c];
#pragma unroll
            for (int i = 0; i < 5; i++) acc[4 + i] += su[43 + k * 5 + i] * w;
        }
    }

    float* dst = g_P2 + ((size_t)(s * CC + c) * NM_TOT + m) * P2STRIDE;
#pragma unroll
    for (int i = 0; i < 9; i++) { dst[2 * i] = acc[i]; dst[2 * i + 1] = acc[i]; }
    dst[18] = 0.f; dst[19] = 0.f;
}

// ---------------------------------------------------------------------------
// f32x2 packed-FMA helpers (sm_103a FFMA2 — only reachable via PTX)
// ---------------------------------------------------------------------------
__device__ __forceinline__ unsigned long long fma2(unsigned long long a, unsigned long long b,
                                                   unsigned long long c)
{
    unsigned long long d;
    asm("fma.rn.f32x2 %0, %1, %2, %3;" : "=l"(d) : "l"(a), "l"(b), "l"(c));
    return d;
}
__device__ __forceinline__ unsigned long long mul2(unsigned long long a, unsigned long long b)
{
    unsigned long long d;
    asm("mul.rn.f32x2 %0, %1, %2;" : "=l"(d) : "l"(a), "l"(b));
    return d;
}
__device__ __forceinline__ unsigned long long pack2(float a, float b)
{
    unsigned long long r;
    asm("mov.b64 %0, {%1, %2};" : "=l"(r) : "f"(a), "f"(b));
    return r;
}
__device__ __forceinline__ void unpack2(unsigned long long v, float& a, float& b)
{
    asm("mov.b64 {%0, %1}, %2;" : "=f"(a), "=f"(b) : "l"(v));
}

// ---------------------------------------------------------------------------
// Main kernel: block = (64-node species group, 2 channels). Warp w = channel
// cb+w; lane handles 2 nodes (lane, lane+32) packed into f32x2 registers.
// Each monomial: 5 shared loads (duplicated P pairs) feed 9 FFMA2 = 18 FMAs.
// grid = (42, 64), block = 64
// ---------------------------------------------------------------------------
__global__ __launch_bounds__(64) void main_kernel(const float* __restrict__ nf,
                                                  float* __restrict__ out)
{
    __shared__ __align__(16) float sP[2 * PROW2];   // 35040 bytes

    int g = blockIdx.x;
    int s = g_gspec[g];
    if (s < 0) return;
    int cb = blockIdx.y * 2;

    // stage duplicated P for 2 consecutive channels (contiguous in g_P2)
    {
        const float4* src = reinterpret_cast<const float4*>(g_P2 + (size_t)(s * CC + cb) * PROW2);
        float4* dst = reinterpret_cast<float4*>(sP);
        for (int i = threadIdx.x; i < 2 * PROW2 / 4; i += 64) dst[i] = src[i];
    }
    __syncthreads();

    int warp = threadIdx.x >> 5;
    int lane = threadIdx.x & 31;
    int c = cb + warp;
    int n0 = g_list[g * 64 + lane];
    int n1 = g_list[g * 64 + 32 + lane];

    unsigned long long x2[9];
    {
        const float* x0p = nf + ((size_t)(n0 < 0 ? 0 : n0) * CC + c) * DD;
        const float* x1p = nf + ((size_t)(n1 < 0 ? 0 : n1) * CC + c) * DD;
#pragma unroll
        for (int i = 0; i < 9; i++) {
            float a = (n0 >= 0) ? x0p[i] : 0.f;
            float b = (n1 >= 0) ? x1p[i] : 0.f;
            x2[i] = pack2(a, b);
        }
    }

    const unsigned long long* spv =
        reinterpret_cast<const unsigned long long*>(sP + warp * PROW2);
    unsigned long long o[9];
#pragma unroll
    for (int i = 0; i < 9; i++) o[i] = 0ULL;   // bit pattern 0 = (+0.f, +0.f)

    int q = 0;
#define FMA9(M2)                                                                  \
    {                                                                             \
        const ulonglong2* bp = reinterpret_cast<const ulonglong2*>(spv + q * 10); \
        ulonglong2 p0 = bp[0], p1 = bp[1], p2 = bp[2], p3 = bp[3];                \
        unsigned long long p8 = (spv + q * 10)[8];                                \
        o[0] = fma2(M2, p0.x, o[0]); o[1] = fma2(M2, p0.y, o[1]);                 \
        o[2] = fma2(M2, p1.x, o[2]); o[3] = fma2(M2, p1.y, o[3]);                 \
        o[4] = fma2(M2, p2.x, o[4]); o[5] = fma2(M2, p2.y, o[5]);                 \
        o[6] = fma2(M2, p3.x, o[6]); o[7] = fma2(M2, p3.y, o[7]);                 \
        o[8] = fma2(M2, p8, o[8]);                                                \
        q++;                                                                      \
    }

    // deg1 (must match decode_m ordering)
#pragma unroll
    for (int a = 0; a < 9; a++) FMA9(x2[a]);
    // deg2 + deg3 interleaved
#pragma unroll
    for (int a = 0; a < 9; a++) {
#pragma unroll
        for (int b = a; b < 9; b++) {
            unsigned long long xab = mul2(x2[a], x2[b]);
            FMA9(xab);
#pragma unroll
            for (int j = b; j < 9; j++) {
                unsigned long long m3 = mul2(xab, x2[j]);
                FMA9(m3);
            }
        }
    }
#undef FMA9

    float r0[9], r1[9];
#pragma unroll
    for (int i = 0; i < 9; i++) unpack2(o[i], r0[i], r1[i]);

    if (n0 >= 0) {
        float* op = out + ((size_t)n0 * CC + c) * DD;
#pragma unroll
        for (int i = 0; i < 9; i++) op[i] = r0[i];
    }
    if (n1 >= 0) {
        float* op = out + ((size_t)n1 * CC + c) * DD;
#pragma unroll
        for (int i = 0; i < 9; i++) op[i] = r1[i];
    }
}

// ---------------------------------------------------------------------------
extern "C" void kernel_launch(void* const* d_in, const int* in_sizes, int n_in,
                              void* d_out, int out_size)
{
    const float* nf   = (const float*)d_in[0];
    const int*   indx = (const int*)d_in[1];

    const float *U3_0e, *U3_1o, *U3_2e, *U2_0e, *U2_1o, *U2_2e, *U1_0e, *U1_1o, *U1_2e;
    const float *W3_0e, *W3_1o, *W3_2e, *W2_0e, *W2_1o, *W2_2e, *W1_0e, *W1_1o, *W1_2e;

    if (in_sizes[3] == 12800) {
        // interleaved (setup_inputs dict order): U3_0e, W3_0e, U3_1o, W3_1o, ...
        U3_0e = (const float*)d_in[2];  W3_0e = (const float*)d_in[3];
        U3_1o = (const float*)d_in[4];  W3_1o = (const float*)d_in[5];
        U3_2e = (const float*)d_in[6];  W3_2e = (const float*)d_in[7];
        U2_0e = (const float*)d_in[8];  W2_0e = (const float*)d_in[9];
        U2_1o = (const float*)d_in[10]; W2_1o = (const float*)d_in[11];
        U2_2e = (const float*)d_in[12]; W2_2e = (const float*)d_in[13];
        U1_0e = (const float*)d_in[14]; W1_0e = (const float*)d_in[15];
        U1_1o = (const float*)d_in[16]; W1_1o = (const float*)d_in[17];
        U1_2e = (const float*)d_in[18]; W1_2e = (const float*)d_in[19];
    } else {
        // grouped (reference signature order): all U's then all W's
        U3_0e = (const float*)d_in[2];  U3_1o = (const float*)d_in[3];
        U3_2e = (const float*)d_in[4];  U2_0e = (const float*)d_in[5];
        U2_1o = (const float*)d_in[6];  U2_2e = (const float*)d_in[7];
        U1_0e = (const float*)d_in[8];  U1_1o = (const float*)d_in[9];
        U1_2e = (const float*)d_in[10];
        W3_0e = (const float*)d_in[11]; W3_1o = (const float*)d_in[12];
        W3_2e = (const float*)d_in[13]; W2_0e = (const float*)d_in[14];
        W2_1o = (const float*)d_in[15]; W2_2e = (const float*)d_in[16];
        W1_0e = (const float*)d_in[17]; W1_1o = (const float*)d_in[18];
        W1_2e = (const float*)d_in[19];
    }

    bucket_kernel<<<1, 256>>>(indx);
    pbuild_kernel<<<dim3(NM_TOT, NSPEC), 128>>>(U3_0e, U3_1o, U3_2e, U2_0e, U2_1o, U2_2e,
                                                U1_0e, U1_1o, U1_2e,
                                                W3_0e, W3_1o, W3_2e, W2_0e, W2_1o, W2_2e,
                                                W1_0e, W1_1o, W1_2e);
    main_kernel<<<dim3(MAXG64, CC / 2), 64>>>(nf, (float*)d_out);
}

// round 7
// speedup vs baseline: 1.2126x; 1.2126x over previous
#include <cuda_runtime.h>

#define NN 2048
#define CC 128
#define NSPEC 10
#define DD 9
#define NM_TOT 219          // 9 (deg1) + 45 (deg2) + 165 (deg3)
#define PSTRIDE 12          // floats per monomial: 9 + 3 pad (48B)
#define PROW (NM_TOT * PSTRIDE)   // 2628 floats per (species, channel)
#define MAXG64 42           // max 64-node groups: 2048/64 + 10

typedef unsigned long long ull;

// Scratch (no cudaMalloc allowed)
__device__ float g_P[(size_t)NSPEC * CC * PROW];   // ~13.5 MB
__device__ int   g_list[MAXG64 * 64];
__device__ int   g_gspec[MAXG64];

// ---------------------------------------------------------------------------
// Monomial ordering: m 0..8 = deg1(a); then for a<=b: deg2(a,b), then for
// j>=b: deg3(a,b,j). Must match the main kernel's unrolled loop.
// ---------------------------------------------------------------------------
__device__ __forceinline__ void decode_m(int m, int& deg, int& A, int& B, int& J, int& sidx)
{
    if (m < 9) { deg = 1; A = m; B = 0; J = 0; sidx = m; return; }
    int mm = 9, s2 = 0, s3 = 0;
    for (int a = 0; a < 9; a++) {
        for (int b = a; b < 9; b++) {
            if (mm == m) { deg = 2; A = a; B = b; J = 0; sidx = s2; return; }
            mm++; s2++;
            for (int j = b; j < 9; j++) {
                if (mm == m) { deg = 3; A = a; B = b; J = j; sidx = s3; return; }
                mm++; s3++;
            }
        }
    }
    deg = 0; A = B = J = sidx = 0;
}

// ---------------------------------------------------------------------------
// Kernel A: bucket nodes by species into 64-aligned groups (padded with -1).
// Warp-aggregated atomics: one atomicAdd per distinct species per warp-pass.
// ---------------------------------------------------------------------------
__global__ void bucket_kernel(const int* __restrict__ index)
{
    __shared__ int cnt[NSPEC];
    __shared__ int cur[NSPEC];
    int t = threadIdx.x;
    int lane = t & 31;
    if (t < NSPEC) cnt[t] = 0;
    __syncthreads();
    for (int n = t; n < NN; n += 1024) {
        int s = index[n];
        unsigned mask = __match_any_sync(0xffffffffu, s);
        int leader = __ffs(mask) - 1;
        if (lane == leader) atomicAdd(&cnt[s], __popc(mask));
    }
    __syncthreads();
    if (t == 0) {
        int off = 0, g = 0;
        for (int s = 0; s < NSPEC; s++) {
            cur[s] = off;
            int grp = (cnt[s] + 63) >> 6;
            for (int k = 0; k < grp; k++) g_gspec[g++] = s;
            off += grp * 64;
        }
        for (; g < MAXG64; g++) g_gspec[g] = -1;
    }
    __syncthreads();
    for (int i = t; i < MAXG64 * 64; i += 1024) g_list[i] = -1;
    __syncthreads();
    for (int n = t; n < NN; n += 1024) {
        int s = index[n];
        unsigned mask = __match_any_sync(0xffffffffu, s);
        int leader = __ffs(mask) - 1;
        int rank = __popc(mask & ((1u << lane) - 1));
        int base = 0;
        if (lane == leader) base = atomicAdd(&cur[s], __popc(mask));
        base = __shfl_sync(mask, base, leader);
        g_list[base + rank] = n;
    }
}

// ---------------------------------------------------------------------------
// Kernel B: fused U-symmetrize + weight contraction -> P table
//   g_P[s][c][m][i] (stride 12). grid = (219, 10), block = 128 (c)
// ---------------------------------------------------------------------------
__global__ void pbuild_kernel(const float* __restrict__ U3_0e, const float* __restrict__ U3_1o,
                              const float* __restrict__ U3_2e,
                              const float* __restrict__ U2_0e, const float* __restrict__ U2_1o,
                              const float* __restrict__ U2_2e,
                              const float* __restrict__ U1_0e, const float* __restrict__ U1_1o,
                              const float* __restrict__ U1_2e,
                              const float* __restrict__ W3_0e, const float* __restrict__ W3_1o,
                              const float* __restrict__ W3_2e,
                              const float* __restrict__ W2_0e, const float* __restrict__ W2_1o,
                              const float* __restrict__ W2_2e,
                              const float* __restrict__ W1_0e, const float* __restrict__ W1_1o,
                              const float* __restrict__ W1_2e)
{
    int m = blockIdx.x;
    int s = blockIdx.y;
    int t = threadIdx.x;
    int deg, A, B, J, sidx;
    decode_m(m, deg, A, B, J, sidx);

    __shared__ float su[108];   // symmetrized U row for this monomial

    if (deg == 1) {
        if (t < 9) {
            float v;
            if (t == 0)      v = U1_0e[A];
            else if (t < 4)  v = U1_1o[A * 3 + (t - 1)];
            else             v = U1_2e[A * 5 + (t - 4)];
            su[t] = v;
        }
    } else if (deg == 2) {
        if (t < 24) {
            int e = t;
            float acc = 0.f;
            int np = (A == B) ? 1 : 2;
            for (int p = 0; p < np; p++) {
                int pa = p ? B : A;
                int pb = p ? A : B;
                int base2 = pa * 9 + pb;
                float v;
                if (e < 3) {
                    v = U2_0e[base2 * 3 + e];
                } else if (e < 9) {
                    int k = (e - 3) / 3, i = (e - 3) % 3;
                    v = U2_1o[(base2 * 2 + k) * 3 + i];
                } else {
                    int k = (e - 9) / 5, i = (e - 9) % 5;
                    v = U2_2e[(base2 * 3 + k) * 5 + i];
                }
                acc += v;
            }
            su[e] = acc;
        }
    } else { // deg 3
        if (t < 108) {
            int e = t;
            int perm[6][3];
            int np;
            if (A == B && B == J) {
                np = 1;
                perm[0][0] = A; perm[0][1] = A; perm[0][2] = A;
            } else if (A == B) {
                np = 3;
                int P[3][3] = {{A, A, J}, {A, J, A}, {J, A, A}};
                for (int p = 0; p < 3; p++) for (int q = 0; q < 3; q++) perm[p][q] = P[p][q];
            } else if (B == J) {
                np = 3;
                int P[3][3] = {{A, B, B}, {B, A, B}, {B, B, A}};
                for (int p = 0; p < 3; p++) for (int q = 0; q < 3; q++) perm[p][q] = P[p][q];
            } else {
                np = 6;
                int P[6][3] = {{A, B, J}, {A, J, B}, {B, A, J}, {B, J, A}, {J, A, B}, {J, B, A}};
                for (int p = 0; p < 6; p++) for (int q = 0; q < 3; q++) perm[p][q] = P[p][q];
            }
            float acc = 0.f;
            for (int p = 0; p < np; p++) {
                int base3 = (perm[p][0] * 9 + perm[p][1]) * 9 + perm[p][2];
                float v;
                if (e < 10) {
                    v = U3_0e[base3 * 10 + e];
                } else if (e < 43) {
                    int k = (e - 10) / 3, i = (e - 10) % 3;
                    v = U3_1o[(base3 * 11 + k) * 3 + i];
                } else {
                    int k = (e - 43) / 5, i = (e - 43) % 5;
                    v = U3_2e[(base3 * 13 + k) * 5 + i];
                }
                acc += v;
            }
            su[e] = acc;
        }
    }
    __syncthreads();

    int c = t;
    float acc[9];
#pragma unroll
    for (int i = 0; i < 9; i++) acc[i] = 0.f;

    if (deg == 1) {
        float w0 = W1_0e[s * CC + c];
        float w1 = W1_1o[s * CC + c];
        float w2 = W1_2e[s * CC + c];
        acc[0] = su[0] * w0;
#pragma unroll
        for (int i = 0; i < 3; i++) acc[1 + i] = su[1 + i] * w1;
#pragma unroll
        for (int i = 0; i < 5; i++) acc[4 + i] = su[4 + i] * w2;
    } else if (deg == 2) {
#pragma unroll
        for (int k = 0; k < 3; k++) {
            float w = W2_0e[(s * 3 + k) * CC + c];
            acc[0] += su[k] * w;
        }
#pragma unroll
        for (int k = 0; k < 2; k++) {
            float w = W2_1o[(s * 2 + k) * CC + c];
#pragma unroll
            for (int i = 0; i < 3; i++) acc[1 + i] += su[3 + k * 3 + i] * w;
        }
#pragma unroll
        for (int k = 0; k < 3; k++) {
            float w = W2_2e[(s * 3 + k) * CC + c];
#pragma unroll
            for (int i = 0; i < 5; i++) acc[4 + i] += su[9 + k * 5 + i] * w;
        }
    } else {
#pragma unroll
        for (int k = 0; k < 10; k++) {
            float w = W3_0e[(s * 10 + k) * CC + c];
            acc[0] += su[k] * w;
        }
#pragma unroll
        for (int k = 0; k < 11; k++) {
            float w = W3_1o[(s * 11 + k) * CC + c];
#pragma unroll
            for (int i = 0; i < 3; i++) acc[1 + i] += su[10 + k * 3 + i] * w;
        }
#pragma unroll
        for (int k = 0; k < 13; k++) {
            float w = W3_2e[(s * 13 + k) * CC + c];
#pragma unroll
            for (int i = 0; i < 5; i++) acc[4 + i] += su[43 + k * 5 + i] * w;
        }
    }

    float* dst = g_P + ((size_t)(s * CC + c) * NM_TOT + m) * PSTRIDE;
#pragma unroll
    for (int i = 0; i < 9; i++) dst[i] = acc[i];
    dst[9] = 0.f; dst[10] = 0.f; dst[11] = 0.f;
}

// ---------------------------------------------------------------------------
// f32x2 packed helpers (sm_103a FFMA2 — only reachable via PTX)
// ---------------------------------------------------------------------------
__device__ __forceinline__ ull fma2(ull a, ull b, ull c)
{
    ull d;
    asm("fma.rn.f32x2 %0, %1, %2, %3;" : "=l"(d) : "l"(a), "l"(b), "l"(c));
    return d;
}
__device__ __forceinline__ ull mul2(ull a, ull b)
{
    ull d;
    asm("mul.rn.f32x2 %0, %1, %2;" : "=l"(d) : "l"(a), "l"(b));
    return d;
}
__device__ __forceinline__ ull pack2(float a, float b)
{
    ull r;
    asm("mov.b64 %0, {%1, %2};" : "=l"(r) : "f"(a), "f"(b));
    return r;
}
__device__ __forceinline__ void unpack2(ull v, float& a, float& b)
{
    asm("mov.b64 {%0, %1}, %2;" : "=f"(a), "=f"(b) : "l"(v));
}

// ---------------------------------------------------------------------------
// Main kernel: block = (64-node species group, 4 channels). Warp w = channel
// cb+w. Lane handles 2 nodes; x is register-duplicated (x_i,x_i) per node so
// mul2 chains give (m,m); P pairs are natural consecutive floats. Per
// monomial per warp: 3 LDS + 10 FFMA2 + 2 MUL2 covering 18 scalar FMAs.
// grid = (42, 32), block = 128
// ---------------------------------------------------------------------------
__global__ __launch_bounds__(128) void main_kernel(const float* __restrict__ nf,
                                                   float* __restrict__ out)
{
    __shared__ __align__(16) float sP[4 * PROW]; // 42048 bytes

    int g = blockIdx.x;
    int s = g_gspec[g];
    if (s < 0) return;
    int cb = blockIdx.y * 4;

    // stage P for 4 consecutive channels (contiguous in g_P)
    {
        const float4* src = reinterpret_cast<const float4*>(g_P + (size_t)(s * CC + cb) * PROW);
        float4* dst = reinterpret_cast<float4*>(sP);
        for (int i = threadIdx.x; i < 4 * PROW / 4; i += 128) dst[i] = src[i];
    }
    __syncthreads();

    int warp = threadIdx.x >> 5;
    int lane = threadIdx.x & 31;
    int c = cb + warp;
    int n0 = g_list[g * 64 + lane];
    int n1 = g_list[g * 64 + 32 + lane];

    ull xa[9], xb[9];   // (x_i, x_i) duplicated per node
    {
        const float* x0p = nf + ((size_t)(n0 < 0 ? 0 : n0) * CC + c) * DD;
        const float* x1p = nf + ((size_t)(n1 < 0 ? 0 : n1) * CC + c) * DD;
#pragma unroll
        for (int i = 0; i < 9; i++) {
            float a = (n0 >= 0) ? x0p[i] : 0.f;
            float b = (n1 >= 0) ? x1p[i] : 0.f;
            xa[i] = pack2(a, a);
            xb[i] = pack2(b, b);
        }
    }

    const ull* spv = reinterpret_cast<const ull*>(sP + warp * PROW);
    ull oa[5], ob[5];   // output pairs (0,1)(2,3)(4,5)(6,7)(8,pad)
#pragma unroll
    for (int i = 0; i < 5; i++) { oa[i] = 0ULL; ob[i] = 0ULL; }

    int q = 0;
#define FMA18(MA, MB)                                                            \
    {                                                                            \
        const ulonglong2* bp = reinterpret_cast<const ulonglong2*>(spv + q * 6); \
        ulonglong2 p0 = bp[0], p1 = bp[1];                                       \
        ull p2 = (spv + q * 6)[4];                                               \
        oa[0] = fma2(MA, p0.x, oa[0]); ob[0] = fma2(MB, p0.x, ob[0]);            \
        oa[1] = fma2(MA, p0.y, oa[1]); ob[1] = fma2(MB, p0.y, ob[1]);            \
        oa[2] = fma2(MA, p1.x, oa[2]); ob[2] = fma2(MB, p1.x, ob[2]);            \
        oa[3] = fma2(MA, p1.y, oa[3]); ob[3] = fma2(MB, p1.y, ob[3]);            \
        oa[4] = fma2(MA, p2, oa[4]);   ob[4] = fma2(MB, p2, ob[4]);              \
        q++;                                                                     \
    }

    // deg1 (must match decode_m ordering)
#pragma unroll
    for (int a = 0; a < 9; a++) FMA18(xa[a], xb[a]);
    // deg2 + deg3 interleaved
#pragma unroll
    for (int a = 0; a < 9; a++) {
#pragma unroll
        for (int b = a; b < 9; b++) {
            ull mab_a = mul2(xa[a], xa[b]);
            ull mab_b = mul2(xb[a], xb[b]);
            FMA18(mab_a, mab_b);
#pragma unroll
            for (int j = b; j < 9; j++) {
                ull m3a = mul2(mab_a, xa[j]);
                ull m3b = mul2(mab_b, xb[j]);
                FMA18(m3a, m3b);
            }
        }
    }
#undef FMA18

    if (n0 >= 0) {
        float r[10];
#pragma unroll
        for (int i = 0; i < 5; i++) unpack2(oa[i], r[2 * i], r[2 * i + 1]);
        float* op = out + ((size_t)n0 * CC + c) * DD;
#pragma unroll
        for (int i = 0; i < 9; i++) op[i] = r[i];
    }
    if (n1 >= 0) {
        float r[10];
#pragma unroll
        for (int i = 0; i < 5; i++) unpack2(ob[i], r[2 * i], r[2 * i + 1]);
        float* op = out + ((size_t)n1 * CC + c) * DD;
#pragma unroll
        for (int i = 0; i < 9; i++) op[i] = r[i];
    }
}

// ---------------------------------------------------------------------------
extern "C" void kernel_launch(void* const* d_in, const int* in_sizes, int n_in,
                              void* d_out, int out_size)
{
    const float* nf   = (const float*)d_in[0];
    const int*   indx = (const int*)d_in[1];

    const float *U3_0e, *U3_1o, *U3_2e, *U2_0e, *U2_1o, *U2_2e, *U1_0e, *U1_1o, *U1_2e;
    const float *W3_0e, *W3_1o, *W3_2e, *W2_0e, *W2_1o, *W2_2e, *W1_0e, *W1_1o, *W1_2e;

    if (in_sizes[3] == 12800) {
        // interleaved (setup_inputs dict order): U3_0e, W3_0e, U3_1o, W3_1o, ...
        U3_0e = (const float*)d_in[2];  W3_0e = (const float*)d_in[3];
        U3_1o = (const float*)d_in[4];  W3_1o = (const float*)d_in[5];
        U3_2e = (const float*)d_in[6];  W3_2e = (const float*)d_in[7];
        U2_0e = (const float*)d_in[8];  W2_0e = (const float*)d_in[9];
        U2_1o = (const float*)d_in[10]; W2_1o = (const float*)d_in[11];
        U2_2e = (const float*)d_in[12]; W2_2e = (const float*)d_in[13];
        U1_0e = (const float*)d_in[14]; W1_0e = (const float*)d_in[15];
        U1_1o = (const float*)d_in[16]; W1_1o = (const float*)d_in[17];
        U1_2e = (const float*)d_in[18]; W1_2e = (const float*)d_in[19];
    } else {
        // grouped (reference signature order): all U's then all W's
        U3_0e = (const float*)d_in[2];  U3_1o = (const float*)d_in[3];
        U3_2e = (const float*)d_in[4];  U2_0e = (const float*)d_in[5];
        U2_1o = (const float*)d_in[6];  U2_2e = (const float*)d_in[7];
        U1_0e = (const float*)d_in[8];  U1_1o = (const float*)d_in[9];
        U1_2e = (const float*)d_in[10];
        W3_0e = (const float*)d_in[11]; W3_1o = (const float*)d_in[12];
        W3_2e = (const float*)d_in[13]; W2_0e = (const float*)d_in[14];
        W2_1o = (const float*)d_in[15]; W2_2e = (const float*)d_in[16];
        W1_0e = (const float*)d_in[17]; W1_1o = (const float*)d_in[18];
        W1_2e = (const float*)d_in[19];
    }

    bucket_kernel<<<1, 1024>>>(indx);
    pbuild_kernel<<<dim3(NM_TOT, NSPEC), 128>>>(U3_0e, U3_1o, U3_2e, U2_0e, U2_1o, U2_2e,
                                                U1_0e, U1_1o, U1_2e,
                                                W3_0e, W3_1o, W3_2e, W2_0e, W2_1o, W2_2e,
                                                W1_0e, W1_1o, W1_2e);
    main_kernel<<<dim3(MAXG64, CC / 4), 128>>>(nf, (float*)d_out);
}

// round 10
// speedup vs baseline: 1.3017x; 1.0734x over previous
#include <cuda_runtime.h>

#define NN 2048
#define CC 128
#define NSPEC 10
#define DD 9
#define NM_TOT 219          // 9 (deg1) + 45 (deg2) + 165 (deg3)
#define PSTRIDE 10          // floats per monomial row: 9 + 1 zero pad (40B, 5 ull)
#define PROW (NM_TOT * PSTRIDE)   // 2190 floats per (species, channel)
#define MAXG64 42           // max 64-node groups: 2048/64 + 10

typedef unsigned long long ull;

// Scratch (no cudaMalloc allowed)
__device__ float g_P[(size_t)NSPEC * CC * PROW];   // ~11.2 MB
__device__ int   g_list[MAXG64 * 64];
__device__ int   g_gspec[MAXG64];

// ---------------------------------------------------------------------------
// Monomial ordering: m 0..8 = deg1(a); then for a<=b: deg2(a,b), then for
// j>=b: deg3(a,b,j). Must match the main kernel's Horner loop.
// ---------------------------------------------------------------------------
__device__ __forceinline__ void decode_m(int m, int& deg, int& A, int& B, int& J, int& sidx)
{
    if (m < 9) { deg = 1; A = m; B = 0; J = 0; sidx = m; return; }
    int mm = 9, s2 = 0, s3 = 0;
    for (int a = 0; a < 9; a++) {
        for (int b = a; b < 9; b++) {
            if (mm == m) { deg = 2; A = a; B = b; J = 0; sidx = s2; return; }
            mm++; s2++;
            for (int j = b; j < 9; j++) {
                if (mm == m) { deg = 3; A = a; B = b; J = j; sidx = s3; return; }
                mm++; s3++;
            }
        }
    }
    deg = 0; A = B = J = sidx = 0;
}

// ---------------------------------------------------------------------------
// Bucketing (device function, run by one extra block of pbuild): group nodes
// by species into 64-aligned groups (padded -1). Warp-aggregated atomics.
// ---------------------------------------------------------------------------
__device__ void bucket_work(const int* __restrict__ index)
{
    __shared__ int cnt[NSPEC];
    __shared__ int cur[NSPEC];
    int t = threadIdx.x;
    int lane = t & 31;
    if (t < NSPEC) cnt[t] = 0;
    __syncthreads();
    for (int n = t; n < NN; n += blockDim.x) {
        int s = index[n];
        unsigned mask = __match_any_sync(0xffffffffu, s);
        int leader = __ffs(mask) - 1;
        if (lane == leader) atomicAdd(&cnt[s], __popc(mask));
    }
    __syncthreads();
    if (t == 0) {
        int off = 0, g = 0;
        for (int s = 0; s < NSPEC; s++) {
            cur[s] = off;
            int grp = (cnt[s] + 63) >> 6;
            for (int k = 0; k < grp; k++) g_gspec[g++] = s;
            off += grp * 64;
        }
        for (; g < MAXG64; g++) g_gspec[g] = -1;
    }
    __syncthreads();
    for (int i = t; i < MAXG64 * 64; i += blockDim.x) g_list[i] = -1;
    __syncthreads();
    for (int n = t; n < NN; n += blockDim.x) {
        int s = index[n];
        unsigned mask = __match_any_sync(0xffffffffu, s);
        int leader = __ffs(mask) - 1;
        int rank = __popc(mask & ((1u << lane) - 1));
        int base = 0;
        if (lane == leader) base = atomicAdd(&cur[s], __popc(mask));
        base = __shfl_sync(mask, base, leader);
        g_list[base + rank] = n;
    }
}

// ---------------------------------------------------------------------------
// Kernel B: fused U-symmetrize + weight contraction -> P table (+ bucketing
// in the extra blockIdx.x == NM_TOT block, concurrent with the rest).
//   g_P[s][c][m][i] (stride 10). grid = (220, 10), block = 128 (c)
// ---------------------------------------------------------------------------
__global__ void pbuild_kernel(const int* __restrict__ index,
                              const float* __restrict__ U3_0e, const float* __restrict__ U3_1o,
                              const float* __restrict__ U3_2e,
                              const float* __restrict__ U2_0e, const float* __restrict__ U2_1o,
                              const float* __restrict__ U2_2e,
                              const float* __restrict__ U1_0e, const float* __restrict__ U1_1o,
                              const float* __restrict__ U1_2e,
                              const float* __restrict__ W3_0e, const float* __restrict__ W3_1o,
                              const float* __restrict__ W3_2e,
                              const float* __restrict__ W2_0e, const float* __restrict__ W2_1o,
                              const float* __restrict__ W2_2e,
                              const float* __restrict__ W1_0e, const float* __restrict__ W1_1o,
                              const float* __restrict__ W1_2e)
{
    int m = blockIdx.x;
    int s = blockIdx.y;
    if (m == NM_TOT) {
        if (s == 0) bucket_work(index);
        return;
    }
    int t = threadIdx.x;
    int deg, A, B, J, sidx;
    decode_m(m, deg, A, B, J, sidx);

    __shared__ float su[108];   // symmetrized U row for this monomial

    if (deg == 1) {
        if (t < 9) {
            float v;
            if (t == 0)      v = U1_0e[A];
            else if (t < 4)  v = U1_1o[A * 3 + (t - 1)];
            else             v = U1_2e[A * 5 + (t - 4)];
            su[t] = v;
        }
    } else if (deg == 2) {
        if (t < 24) {
            int e = t;
            float acc = 0.f;
            int np = (A == B) ? 1 : 2;
            for (int p = 0; p < np; p++) {
                int pa = p ? B : A;
                int pb = p ? A : B;
                int base2 = pa * 9 + pb;
                float v;
                if (e < 3) {
                    v = U2_0e[base2 * 3 + e];
                } else if (e < 9) {
                    int k = (e - 3) / 3, i = (e - 3) % 3;
                    v = U2_1o[(base2 * 2 + k) * 3 + i];
                } else {
                    int k = (e - 9) / 5, i = (e - 9) % 5;
                    v = U2_2e[(base2 * 3 + k) * 5 + i];
                }
                acc += v;
            }
            su[e] = acc;
        }
    } else { // deg 3
        if (t < 108) {
            int e = t;
            int perm[6][3];
            int np;
            if (A == B && B == J) {
                np = 1;
                perm[0][0] = A; perm[0][1] = A; perm[0][2] = A;
            } else if (A == B) {
                np = 3;
                int P[3][3] = {{A, A, J}, {A, J, A}, {J, A, A}};
                for (int p = 0; p < 3; p++) for (int q = 0; q < 3; q++) perm[p][q] = P[p][q];
            } else if (B == J) {
                np = 3;
                int P[3][3] = {{A, B, B}, {B, A, B}, {B, B, A}};
                for (int p = 0; p < 3; p++) for (int q = 0; q < 3; q++) perm[p][q] = P[p][q];
            } else {
                np = 6;
                int P[6][3] = {{A, B, J}, {A, J, B}, {B, A, J}, {B, J, A}, {J, A, B}, {J, B, A}};
                for (int p = 0; p < 6; p++) for (int q = 0; q < 3; q++) perm[p][q] = P[p][q];
            }
            float acc = 0.f;
            for (int p = 0; p < np; p++) {
                int base3 = (perm[p][0] * 9 + perm[p][1]) * 9 + perm[p][2];
                float v;
                if (e < 10) {
                    v = U3_0e[base3 * 10 + e];
                } else if (e < 43) {
                    int k = (e - 10) / 3, i = (e - 10) % 3;
                    v = U3_1o[(base3 * 11 + k) * 3 + i];
                } else {
                    int k = (e - 43) / 5, i = (e - 43) % 5;
                    v = U3_2e[(base3 * 13 + k) * 5 + i];
                }
                acc += v;
            }
            su[e] = acc;
        }
    }
    __syncthreads();

    int c = t;
    float acc[9];
#pragma unroll
    for (int i = 0; i < 9; i++) acc[i] = 0.f;

    if (deg == 1) {
        float w0 = W1_0e[s * CC + c];
        float w1 = W1_1o[s * CC + c];
        float w2 = W1_2e[s * CC + c];
        acc[0] = su[0] * w0;
#pragma unroll
        for (int i = 0; i < 3; i++) acc[1 + i] = su[1 + i] * w1;
#pragma unroll
        for (int i = 0; i < 5; i++) acc[4 + i] = su[4 + i] * w2;
    } else if (deg == 2) {
#pragma unroll
        for (int k = 0; k < 3; k++) {
            float w = W2_0e[(s * 3 + k) * CC + c];
            acc[0] += su[k] * w;
        }
#pragma unroll
        for (int k = 0; k < 2; k++) {
            float w = W2_1o[(s * 2 + k) * CC + c];
#pragma unroll
            for (int i = 0; i < 3; i++) acc[1 + i] += su[3 + k * 3 + i] * w;
        }
#pragma unroll
        for (int k = 0; k < 3; k++) {
            float w = W2_2e[(s * 3 + k) * CC + c];
#pragma unroll
            for (int i = 0; i < 5; i++) acc[4 + i] += su[9 + k * 5 + i] * w;
        }
    } else {
#pragma unroll
        for (int k = 0; k < 10; k++) {
            float w = W3_0e[(s * 10 + k) * CC + c];
            acc[0] += su[k] * w;
        }
#pragma unroll
        for (int k = 0; k < 11; k++) {
            float w = W3_1o[(s * 11 + k) * CC + c];
#pragma unroll
            for (int i = 0; i < 3; i++) acc[1 + i] += su[10 + k * 3 + i] * w;
        }
#pragma unroll
        for (int k = 0; k < 13; k++) {
            float w = W3_2e[(s * 13 + k) * CC + c];
#pragma unroll
            for (int i = 0; i < 5; i++) acc[4 + i] += su[43 + k * 5 + i] * w;
        }
    }

    float* dst = g_P + ((size_t)(s * CC + c) * NM_TOT + m) * PSTRIDE;
#pragma unroll
    for (int i = 0; i < 9; i++) dst[i] = acc[i];
    dst[9] = 0.f;
}

// ---------------------------------------------------------------------------
// f32x2 packed helpers (sm_103a FFMA2 — only reachable via PTX)
// ---------------------------------------------------------------------------
__device__ __forceinline__ ull fma2(ull a, ull b, ull c)
{
    ull d;
    asm("fma.rn.f32x2 %0, %1, %2, %3;" : "=l"(d) : "l"(a), "l"(b), "l"(c));
    return d;
}
__device__ __forceinline__ ull pack2(float a, float b)
{
    ull r;
    asm("mov.b64 %0, {%1, %2};" : "=l"(r) : "f"(a), "f"(b));
    return r;
}
__device__ __forceinline__ void unpack2(ull v, float& a, float& b)
{
    asm("mov.b64 {%0, %1}, %2;" : "=f"(a), "=f"(b) : "l"(v));
}

// ---------------------------------------------------------------------------
// Main kernel: Horner form. block = (64-node species group, 4 channels).
// Warp w = channel cb+w; lane handles 2 nodes with duplicated-x f32x2 regs.
//   out = sum_a x_a * (P1_a + sum_{b>=a} x_b * (P2_ab + sum_{j>=b} x_j * P3_abj))
// Zero MUL2s: all monomial building folds into the FFMA2 chains.
// grid = (42, 32), block = 128, smem 35KB -> 6 blocks (24 warps)/SM
// ---------------------------------------------------------------------------
__global__ __launch_bounds__(128) void main_kernel(const float* __restrict__ nf,
                                                   float* __restrict__ out)
{
    __shared__ __align__(16) float sP[4 * PROW]; // 35040 bytes

    int g = blockIdx.x;
    int s = g_gspec[g];
    if (s < 0) return;
    int cb = blockIdx.y * 4;

    // stage P for 4 consecutive channels (contiguous, 16B-aligned slab)
    {
        const float4* src = reinterpret_cast<const float4*>(g_P + (size_t)(s * CC + cb) * PROW);
        float4* dst = reinterpret_cast<float4*>(sP);
        for (int i = threadIdx.x; i < 4 * PROW / 4; i += 128) dst[i] = src[i];
    }
    __syncthreads();

    int warp = threadIdx.x >> 5;
    int lane = threadIdx.x & 31;
    int c = cb + warp;
    int n0 = g_list[g * 64 + lane];
    int n1 = g_list[g * 64 + 32 + lane];

    ull xa[9], xb[9];   // (x_i, x_i) duplicated per node
    {
        const float* x0p = nf + ((size_t)(n0 < 0 ? 0 : n0) * CC + c) * DD;
        const float* x1p = nf + ((size_t)(n1 < 0 ? 0 : n1) * CC + c) * DD;
#pragma unroll
        for (int i = 0; i < 9; i++) {
            float a = (n0 >= 0) ? x0p[i] : 0.f;
            float b = (n1 >= 0) ? x1p[i] : 0.f;
            xa[i] = pack2(a, a);
            xb[i] = pack2(b, b);
        }
    }

    const ull* spv = reinterpret_cast<const ull*>(sP + warp * PROW); // warp*8760B, 8-aligned
    ull oa[5], ob[5];   // output pairs (0,1)(2,3)(4,5)(6,7)(8,pad)
#pragma unroll
    for (int i = 0; i < 5; i++) { oa[i] = 0ULL; ob[i] = 0ULL; }

#define LROW(R, ROW)                              \
    {                                             \
        const ull* _p = spv + (ROW) * 5;          \
        R[0] = _p[0]; R[1] = _p[1]; R[2] = _p[2]; \
        R[3] = _p[3]; R[4] = _p[4];               \
    }

    int q = 9;   // row cursor past the 9 deg1 rows (constant-folded by unroll)
#pragma unroll
    for (int a = 0; a < 9; a++) {
        ull p1r[5];
        LROW(p1r, a);
        ull Ra[5], Rb[5];
#pragma unroll
        for (int b = a; b < 9; b++) {
            ull p2r[5];
            LROW(p2r, q); q++;
            ull pr[5];
            LROW(pr, q); q++;     // deg3 row j = b
            ull Ta[5], Tb[5];
#pragma unroll
            for (int i = 0; i < 5; i++) {
                Ta[i] = fma2(xa[b], pr[i], p2r[i]);
                Tb[i] = fma2(xb[b], pr[i], p2r[i]);
            }
#pragma unroll
            for (int j = b + 1; j < 9; j++) {
                LROW(pr, q); q++;
#pragma unroll
                for (int i = 0; i < 5; i++) {
                    Ta[i] = fma2(xa[j], pr[i], Ta[i]);
                    Tb[i] = fma2(xb[j], pr[i], Tb[i]);
                }
            }
            if (b == a) {
#pragma unroll
                for (int i = 0; i < 5; i++) {
                    Ra[i] = fma2(xa[b], Ta[i], p1r[i]);
                    Rb[i] = fma2(xb[b], Tb[i], p1r[i]);
                }
            } else {
#pragma unroll
                for (int i = 0; i < 5; i++) {
                    Ra[i] = fma2(xa[b], Ta[i], Ra[i]);
                    Rb[i] = fma2(xb[b], Tb[i], Rb[i]);
                }
            }
        }
#pragma unroll
        for (int i = 0; i < 5; i++) {
            oa[i] = fma2(xa[a], Ra[i], oa[i]);
            ob[i] = fma2(xb[a], Rb[i], ob[i]);
        }
    }
#undef LROW

    if (n0 >= 0) {
        float r[10];
#pragma unroll
        for (int i = 0; i < 5; i++) unpack2(oa[i], r[2 * i], r[2 * i + 1]);
        float* op = out + ((size_t)n0 * CC + c) * DD;
#pragma unroll
        for (int i = 0; i < 9; i++) op[i] = r[i];
    }
    if (n1 >= 0) {
        float r[10];
#pragma unroll
        for (int i = 0; i < 5; i++) unpack2(ob[i], r[2 * i], r[2 * i + 1]);
        float* op = out + ((size_t)n1 * CC + c) * DD;
#pragma unroll
        for (int i = 0; i < 9; i++) op[i] = r[i];
    }
}

// ---------------------------------------------------------------------------
extern "C" void kernel_launch(void* const* d_in, const int* in_sizes, int n_in,
                              void* d_out, int out_size)
{
    const float* nf   = (const float*)d_in[0];
    const int*   indx = (const int*)d_in[1];

    const float *U3_0e, *U3_1o, *U3_2e, *U2_0e, *U2_1o, *U2_2e, *U1_0e, *U1_1o, *U1_2e;
    const float *W3_0e, *W3_1o, *W3_2e, *W2_0e, *W2_1o, *W2_2e, *W1_0e, *W1_1o, *W1_2e;

    if (in_sizes[3] == 12800) {
        // interleaved (setup_inputs dict order): U3_0e, W3_0e, U3_1o, W3_1o, ...
        U3_0e = (const float*)d_in[2];  W3_0e = (const float*)d_in[3];
        U3_1o = (const float*)d_in[4];  W3_1o = (const float*)d_in[5];
        U3_2e = (const float*)d_in[6];  W3_2e = (const float*)d_in[7];
        U2_0e = (const float*)d_in[8];  W2_0e = (const float*)d_in[9];
        U2_1o = (const float*)d_in[10]; W2_1o = (const float*)d_in[11];
        U2_2e = (const float*)d_in[12]; W2_2e = (const float*)d_in[13];
        U1_0e = (const float*)d_in[14]; W1_0e = (const float*)d_in[15];
        U1_1o = (const float*)d_in[16]; W1_1o = (const float*)d_in[17];
        U1_2e = (const float*)d_in[18]; W1_2e = (const float*)d_in[19];
    } else {
        // grouped (reference signature order): all U's then all W's
        U3_0e = (const float*)d_in[2];  U3_1o = (const float*)d_in[3];
        U3_2e = (const float*)d_in[4];  U2_0e = (const float*)d_in[5];
        U2_1o = (const float*)d_in[6];  U2_2e = (const float*)d_in[7];
        U1_0e = (const float*)d_in[8];  U1_1o = (const float*)d_in[9];
        U1_2e = (const float*)d_in[10];
        W3_0e = (const float*)d_in[11]; W3_1o = (const float*)d_in[12];
        W3_2e = (const float*)d_in[13]; W2_0e = (const float*)d_in[14];
        W2_1o = (const float*)d_in[15]; W2_2e = (const float*)d_in[16];
        W1_0e = (const float*)d_in[17]; W1_1o = (const float*)d_in[18];
        W1_2e = (const float*)d_in[19];
    }

    pbuild_kernel<<<dim3(NM_TOT + 1, NSPEC), 128>>>(indx,
                                                    U3_0e, U3_1o, U3_2e, U2_0e, U2_1o, U2_2e,
                                                    U1_0e, U1_1o, U1_2e,
                                                    W3_0e, W3_1o, W3_2e, W2_0e, W2_1o, W2_2e,
                                                    W1_0e, W1_1o, W1_2e);
    main_kernel<<<dim3(MAXG64, CC / 4), 128>>>(nf, (float*)d_out);
}

// round 14
// speedup vs baseline: 1.3702x; 1.0527x over previous
#include <cuda_runtime.h>

#define NN 2048
#define CC 128
#define NSPEC 10
#define DD 9
#define NM_TOT 219          // 9 (deg1) + 45 (deg2) + 165 (deg3)
#define PSTRIDE 12          // floats per monomial row: 9 + 3 zero pad (48B = 3x16B)
#define PROW (NM_TOT * PSTRIDE)   // 2628 floats per (species, channel)
#define MAXG64 42           // max 64-node groups: 2048/64 + 10

typedef unsigned long long ull;

// Scratch (no cudaMalloc allowed)
__device__ float g_P[(size_t)NSPEC * CC * PROW];   // ~13.5 MB
__device__ int   g_list[MAXG64 * 64];
__device__ int   g_gspec[MAXG64];

// ---------------------------------------------------------------------------
// Monomial ordering: m 0..8 = deg1(a); then for a<=b: deg2(a,b), then for
// j>=b: deg3(a,b,j). Must match the main kernel's Horner loop.
// ---------------------------------------------------------------------------
__device__ __forceinline__ void decode_m(int m, int& deg, int& A, int& B, int& J, int& sidx)
{
    if (m < 9) { deg = 1; A = m; B = 0; J = 0; sidx = m; return; }
    int mm = 9, s2 = 0, s3 = 0;
    for (int a = 0; a < 9; a++) {
        for (int b = a; b < 9; b++) {
            if (mm == m) { deg = 2; A = a; B = b; J = 0; sidx = s2; return; }
            mm++; s2++;
            for (int j = b; j < 9; j++) {
                if (mm == m) { deg = 3; A = a; B = b; J = j; sidx = s3; return; }
                mm++; s3++;
            }
        }
    }
    deg = 0; A = B = J = sidx = 0;
}

// ---------------------------------------------------------------------------
// Bucketing (device function, run by one extra block of pbuild): group nodes
// by species into 64-aligned groups (padded -1). Warp-aggregated atomics.
// ---------------------------------------------------------------------------
__device__ void bucket_work(const int* __restrict__ index)
{
    __shared__ int cnt[NSPEC];
    __shared__ int cur[NSPEC];
    int t = threadIdx.x;
    int lane = t & 31;
    if (t < NSPEC) cnt[t] = 0;
    __syncthreads();
    for (int n = t; n < NN; n += blockDim.x) {
        int s = index[n];
        unsigned mask = __match_any_sync(0xffffffffu, s);
        int leader = __ffs(mask) - 1;
        if (lane == leader) atomicAdd(&cnt[s], __popc(mask));
    }
    __syncthreads();
    if (t == 0) {
        int off = 0, g = 0;
        for (int s = 0; s < NSPEC; s++) {
            cur[s] = off;
            int grp = (cnt[s] + 63) >> 6;
            for (int k = 0; k < grp; k++) g_gspec[g++] = s;
            off += grp * 64;
        }
        for (; g < MAXG64; g++) g_gspec[g] = -1;
    }
    __syncthreads();
    for (int i = t; i < MAXG64 * 64; i += blockDim.x) g_list[i] = -1;
    __syncthreads();
    for (int n = t; n < NN; n += blockDim.x) {
        int s = index[n];
        unsigned mask = __match_any_sync(0xffffffffu, s);
        int leader = __ffs(mask) - 1;
        int rank = __popc(mask & ((1u << lane) - 1));
        int base = 0;
        if (lane == leader) base = atomicAdd(&cur[s], __popc(mask));
        base = __shfl_sync(mask, base, leader);
        g_list[base + rank] = n;
    }
}

// ---------------------------------------------------------------------------
// Kernel B: fused U-symmetrize + weight contraction -> P table (+ bucketing
// in the extra blockIdx.x == NM_TOT block, concurrent with the rest).
//   g_P[s][c][m][i] (stride 12). grid = (220, 10), block = 128 (c)
// ---------------------------------------------------------------------------
__global__ void pbuild_kernel(const int* __restrict__ index,
                              const float* __restrict__ U3_0e, const float* __restrict__ U3_1o,
                              const float* __restrict__ U3_2e,
                              const float* __restrict__ U2_0e, const float* __restrict__ U2_1o,
                              const float* __restrict__ U2_2e,
                              const float* __restrict__ U1_0e, const float* __restrict__ U1_1o,
                              const float* __restrict__ U1_2e,
                              const float* __restrict__ W3_0e, const float* __restrict__ W3_1o,
                              const float* __restrict__ W3_2e,
                              const float* __restrict__ W2_0e, const float* __restrict__ W2_1o,
                              const float* __restrict__ W2_2e,
                              const float* __restrict__ W1_0e, const float* __restrict__ W1_1o,
                              const float* __restrict__ W1_2e)
{
    int m = blockIdx.x;
    int s = blockIdx.y;
    if (m == NM_TOT) {
        if (s == 0) bucket_work(index);
        return;
    }
    int t = threadIdx.x;
    int deg, A, B, J, sidx;
    decode_m(m, deg, A, B, J, sidx);

    __shared__ float su[108];   // symmetrized U row for this monomial

    if (deg == 1) {
        if (t < 9) {
            float v;
            if (t == 0)      v = U1_0e[A];
            else if (t < 4)  v = U1_1o[A * 3 + (t - 1)];
            else             v = U1_2e[A * 5 + (t - 4)];
            su[t] = v;
        }
    } else if (deg == 2) {
        if (t < 24) {
            int e = t;
            float acc = 0.f;
            int np = (A == B) ? 1 : 2;
            for (int p = 0; p < np; p++) {
                int pa = p ? B : A;
                int pb = p ? A : B;
                int base2 = pa * 9 + pb;
                float v;
                if (e < 3) {
                    v = U2_0e[base2 * 3 + e];
                } else if (e < 9) {
                    int k = (e - 3) / 3, i = (e - 3) % 3;
                    v = U2_1o[(base2 * 2 + k) * 3 + i];
                } else {
                    int k = (e - 9) / 5, i = (e - 9) % 5;
                    v = U2_2e[(base2 * 3 + k) * 5 + i];
                }
                acc += v;
            }
            su[e] = acc;
        }
    } else { // deg 3
        if (t < 108) {
            int e = t;
            int perm[6][3];
            int np;
            if (A == B && B == J) {
                np = 1;
                perm[0][0] = A; perm[0][1] = A; perm[0][2] = A;
            } else if (A == B) {
                np = 3;
                int P[3][3] = {{A, A, J}, {A, J, A}, {J, A, A}};
                for (int p = 0; p < 3; p++) for (int q = 0; q < 3; q++) perm[p][q] = P[p][q];
            } else if (B == J) {
                np = 3;
                int P[3][3] = {{A, B, B}, {B, A, B}, {B, B, A}};
                for (int p = 0; p < 3; p++) for (int q = 0; q < 3; q++) perm[p][q] = P[p][q];
            } else {
                np = 6;
                int P[6][3] = {{A, B, J}, {A, J, B}, {B, A, J}, {B, J, A}, {J, A, B}, {J, B, A}};
                for (int p = 0; p < 6; p++) for (int q = 0; q < 3; q++) perm[p][q] = P[p][q];
            }
            float acc = 0.f;
            for (int p = 0; p < np; p++) {
                int base3 = (perm[p][0] * 9 + perm[p][1]) * 9 + perm[p][2];
                float v;
                if (e < 10) {
                    v = U3_0e[base3 * 10 + e];
                } else if (e < 43) {
                    int k = (e - 10) / 3, i = (e - 10) % 3;
                    v = U3_1o[(base3 * 11 + k) * 3 + i];
                } else {
                    int k = (e - 43) / 5, i = (e - 43) % 5;
                    v = U3_2e[(base3 * 13 + k) * 5 + i];
                }
                acc += v;
            }
            su[e] = acc;
        }
    }
    __syncthreads();

    int c = t;
    float acc[9];
#pragma unroll
    for (int i = 0; i < 9; i++) acc[i] = 0.f;

    if (deg == 1) {
        float w0 = W1_0e[s * CC + c];
        float w1 = W1_1o[s * CC + c];
        float w2 = W1_2e[s * CC + c];
        acc[0] = su[0] * w0;
#pragma unroll
        for (int i = 0; i < 3; i++) acc[1 + i] = su[1 + i] * w1;
#pragma unroll
        for (int i = 0; i < 5; i++) acc[4 + i] = su[4 + i] * w2;
    } else if (deg == 2) {
#pragma unroll
        for (int k = 0; k < 3; k++) {
            float w = W2_0e[(s * 3 + k) * CC + c];
            acc[0] += su[k] * w;
        }
#pragma unroll
        for (int k = 0; k < 2; k++) {
            float w = W2_1o[(s * 2 + k) * CC + c];
#pragma unroll
            for (int i = 0; i < 3; i++) acc[1 + i] += su[3 + k * 3 + i] * w;
        }
#pragma unroll
        for (int k = 0; k < 3; k++) {
            float w = W2_2e[(s * 3 + k) * CC + c];
#pragma unroll
            for (int i = 0; i < 5; i++) acc[4 + i] += su[9 + k * 5 + i] * w;
        }
    } else {
#pragma unroll
        for (int k = 0; k < 10; k++) {
            float w = W3_0e[(s * 10 + k) * CC + c];
            acc[0] += su[k] * w;
        }
#pragma unroll
        for (int k = 0; k < 11; k++) {
            float w = W3_1o[(s * 11 + k) * CC + c];
#pragma unroll
            for (int i = 0; i < 3; i++) acc[1 + i] += su[10 + k * 3 + i] * w;
        }
#pragma unroll
        for (int k = 0; k < 13; k++) {
            float w = W3_2e[(s * 13 + k) * CC + c];
#pragma unroll
            for (int i = 0; i < 5; i++) acc[4 + i] += su[43 + k * 5 + i] * w;
        }
    }

    float* dst = g_P + ((size_t)(s * CC + c) * NM_TOT + m) * PSTRIDE;
#pragma unroll
    for (int i = 0; i < 9; i++) dst[i] = acc[i];
    dst[9] = 0.f; dst[10] = 0.f; dst[11] = 0.f;
}

// ---------------------------------------------------------------------------
// f32x2 packed helpers (sm_103a FFMA2 — only reachable via PTX)
// ---------------------------------------------------------------------------
__device__ __forceinline__ ull fma2(ull a, ull b, ull c)
{
    ull d;
    asm("fma.rn.f32x2 %0, %1, %2, %3;" : "=l"(d) : "l"(a), "l"(b), "l"(c));
    return d;
}
__device__ __forceinline__ ull pack2(float a, float b)
{
    ull r;
    asm("mov.b64 %0, {%1, %2};" : "=l"(r) : "f"(a), "f"(b));
    return r;
}
__device__ __forceinline__ void unpack2(ull v, float& a, float& b)
{
    asm("mov.b64 {%0, %1}, %2;" : "=f"(a), "=f"(b) : "l"(v));
}

// ---------------------------------------------------------------------------
// Main kernel: Horner form. block = (64-node species group, 4 channels).
// Warp w = channel cb+w; lane handles 2 nodes with duplicated-x f32x2 regs.
//   out = sum_a x_a * (P1_a + sum_{b>=a} x_b * (P2_ab + sum_{j>=b} x_j * P3_abj))
// P rows are 48B (16B-aligned): 3 x LDS.128 per row (657 LDS/task, was 1095).
// grid = (42, 32), block = 128, smem 42KB -> 5 blocks (20 warps)/SM
// ---------------------------------------------------------------------------
__global__ __launch_bounds__(128, 5) void main_kernel(const float* __restrict__ nf,
                                                      float* __restrict__ out)
{
    __shared__ __align__(16) float sP[4 * PROW]; // 42048 bytes

    int g = blockIdx.x;
    int s = g_gspec[g];
    if (s < 0) return;
    int cb = blockIdx.y * 4;

    // stage P for 4 consecutive channels (contiguous, 16B-aligned slab)
    {
        const float4* src = reinterpret_cast<const float4*>(g_P + (size_t)(s * CC + cb) * PROW);
        float4* dst = reinterpret_cast<float4*>(sP);
        for (int i = threadIdx.x; i < 4 * PROW / 4; i += 128) dst[i] = src[i];
    }
    __syncthreads();

    int warp = threadIdx.x >> 5;
    int lane = threadIdx.x & 31;
    int c = cb + warp;
    int n0 = g_list[g * 64 + lane];
    int n1 = g_list[g * 64 + 32 + lane];

    ull xa[9], xb[9];   // (x_i, x_i) duplicated per node
    {
        const float* x0p = nf + ((size_t)(n0 < 0 ? 0 : n0) * CC + c) * DD;
        const float* x1p = nf + ((size_t)(n1 < 0 ? 0 : n1) * CC + c) * DD;
#pragma unroll
        for (int i = 0; i < 9; i++) {
            float a = (n0 >= 0) ? x0p[i] : 0.f;
            float b = (n1 >= 0) ? x1p[i] : 0.f;
            xa[i] = pack2(a, a);
            xb[i] = pack2(b, b);
        }
    }

    // warp slab: warp*PROW floats = warp*10512B (16B-aligned); rows 48B apart
    const ulonglong2* spv = reinterpret_cast<const ulonglong2*>(sP + warp * PROW);
    ull oa[5], ob[5];   // output pairs (0,1)(2,3)(4,5)(6,7)(8,pad)
#pragma unroll
    for (int i = 0; i < 5; i++) { oa[i] = 0ULL; ob[i] = 0ULL; }

#define LROW(R, ROW)                                      \
    {                                                     \
        const ulonglong2* _p = spv + (ROW) * 3;           \
        ulonglong2 _q0 = _p[0], _q1 = _p[1], _q2 = _p[2]; \
        R[0] = _q0.x; R[1] = _q0.y;                       \
        R[2] = _q1.x; R[3] = _q1.y;                       \
        R[4] = _q2.x;                                     \
    }

    int q = 9;   // row cursor past the 9 deg1 rows (constant-folded by unroll)
#pragma unroll
    for (int a = 0; a < 9; a++) {
        ull p1r[5];
        LROW(p1r, a);
        ull Ra[5], Rb[5];
#pragma unroll
        for (int b = a; b < 9; b++) {
            ull p2r[5];
            LROW(p2r, q); q++;
            ull pr[5];
            LROW(pr, q); q++;     // deg3 row j = b
            ull Ta[5], Tb[5];
#pragma unroll
            for (int i = 0; i < 5; i++) {
                Ta[i] = fma2(xa[b], pr[i], p2r[i]);
                Tb[i] = fma2(xb[b], pr[i], p2r[i]);
            }
#pragma unroll
            for (int j = b + 1; j < 9; j++) {
                LROW(pr, q); q++;
#pragma unroll
                for (int i = 0; i < 5; i++) {
                    Ta[i] = fma2(xa[j], pr[i], Ta[i]);
                    Tb[i] = fma2(xb[j], pr[i], Tb[i]);
                }
            }
            if (b == a) {
#pragma unroll
                for (int i = 0; i < 5; i++) {
                    Ra[i] = fma2(xa[b], Ta[i], p1r[i]);
                    Rb[i] = fma2(xb[b], Tb[i], p1r[i]);
                }
            } else {
#pragma unroll
                for (int i = 0; i < 5; i++) {
                    Ra[i] = fma2(xa[b], Ta[i], Ra[i]);
                    Rb[i] = fma2(xb[b], Tb[i], Rb[i]);
                }
            }
        }
#pragma unroll
        for (int i = 0; i < 5; i++) {
            oa[i] = fma2(xa[a], Ra[i], oa[i]);
            ob[i] = fma2(xb[a], Rb[i], ob[i]);
        }
    }
#undef LROW

    if (n0 >= 0) {
        float r[10];
#pragma unroll
        for (int i = 0; i < 5; i++) unpack2(oa[i], r[2 * i], r[2 * i + 1]);
        float* op = out + ((size_t)n0 * CC + c) * DD;
#pragma unroll
        for (int i = 0; i < 9; i++) op[i] = r[i];
    }
    if (n1 >= 0) {
        float r[10];
#pragma unroll
        for (int i = 0; i < 5; i++) unpack2(ob[i], r[2 * i], r[2 * i + 1]);
        float* op = out + ((size_t)n1 * CC + c) * DD;
#pragma unroll
        for (int i = 0; i < 9; i++) op[i] = r[i];
    }
}

// ---------------------------------------------------------------------------
extern "C" void kernel_launch(void* const* d_in, const int* in_sizes, int n_in,
                              void* d_out, int out_size)
{
    const float* nf   = (const float*)d_in[0];
    const int*   indx = (const int*)d_in[1];

    const float *U3_0e, *U3_1o, *U3_2e, *U2_0e, *U2_1o, *U2_2e, *U1_0e, *U1_1o, *U1_2e;
    const float *W3_0e, *W3_1o, *W3_2e, *W2_0e, *W2_1o, *W2_2e, *W1_0e, *W1_1o, *W1_2e;

    if (in_sizes[3] == 12800) {
        // interleaved (setup_inputs dict order): U3_0e, W3_0e, U3_1o, W3_1o, ...
        U3_0e = (const float*)d_in[2];  W3_0e = (const float*)d_in[3];
        U3_1o = (const float*)d_in[4];  W3_1o = (const float*)d_in[5];
        U3_2e = (const float*)d_in[6];  W3_2e = (const float*)d_in[7];
        U2_0e = (const float*)d_in[8];  W2_0e = (const float*)d_in[9];
        U2_1o = (const float*)d_in[10]; W2_1o = (const float*)d_in[11];
        U2_2e = (const float*)d_in[12]; W2_2e = (const float*)d_in[13];
        U1_0e = (const float*)d_in[14]; W1_0e = (const float*)d_in[15];
        U1_1o = (const float*)d_in[16]; W1_1o = (const float*)d_in[17];
        U1_2e = (const float*)d_in[18]; W1_2e = (const float*)d_in[19];
    } else {
        // grouped (reference signature order): all U's then all W's
        U3_0e = (const float*)d_in[2];  U3_1o = (const float*)d_in[3];
        U3_2e = (const float*)d_in[4];  U2_0e = (const float*)d_in[5];
        U2_1o = (const float*)d_in[6];  U2_2e = (const float*)d_in[7];
        U1_0e = (const float*)d_in[8];  U1_1o = (const float*)d_in[9];
        U1_2e = (const float*)d_in[10];
        W3_0e = (const float*)d_in[11]; W3_1o = (const float*)d_in[12];
        W3_2e = (const float*)d_in[13]; W2_0e = (const float*)d_in[14];
        W2_1o = (const float*)d_in[15]; W2_2e = (const float*)d_in[16];
        W1_0e = (const float*)d_in[17]; W1_1o = (const float*)d_in[18];
        W1_2e = (const float*)d_in[19];
    }

    pbuild_kernel<<<dim3(NM_TOT + 1, NSPEC), 128>>>(indx,
                                                    U3_0e, U3_1o, U3_2e, U2_0e, U2_1o, U2_2e,
                                                    U1_0e, U1_1o, U1_2e,
                                                    W3_0e, W3_1o, W3_2e, W2_0e, W2_1o, W2_2e,
                                                    W1_0e, W1_1o, W1_2e);
    main_kernel<<<dim3(MAXG64, CC / 4), 128>>>(nf, (float*)d_out);
}